// round 11
// baseline (speedup 1.0000x reference)
#include <cuda_runtime.h>
#include <cuda_bf16.h>
#include <stdint.h>

// Round 9: warp-PAIR split-bf16 HMMA kernel.
// Each 2-warp pair processes independent 32-row chunks; within a pair each
// warp owns 64 of the 128 output columns (B smem traffic per point -> 1/4 of
// round 8). Pair-local named barriers only; pairs drift independently.

#define NTHREADS 256
#define NWARPS   8
#define NPAIRS   4

// ---- smem byte offsets ----
#define SM_W0T_HI  0         // [128 n][48 k] bf16, stride 112
#define SM_W0T_LO  14336
#define SM_W1T_HI  28672     // [128 n][128 k] bf16, stride 272
#define SM_W1T_LO  63488
#define SM_A_HI    98304     // 4 pairs x [32][48+pad] bf16, stride 112 (3584 B/pair)
#define SM_A_LO    112640
#define SM_H_HI    126976    // 4 pairs x [32][128+pad] bf16, stride 272 (8704 B/pair)
#define SM_H_LO    161792
#define SM_B1      196608    // 128 f32
#define SM_W2      197120    // 384 f32
#define SM_B2      198656    // 3 f32
#define SM_BIASW   198672    // 4 pairs x 128 f32 fused bias0
#define SM_PART    200720    // 4 pairs x 32 x 3 f32
#define SMEM_TOTAL 202256

#define W0T_STRIDE 112
#define W1T_STRIDE 272
#define A_STRIDE   112
#define H_STRIDE   272

__device__ __forceinline__ uint32_t smem_u32(const void* p) {
    uint32_t a;
    asm("{ .reg .u64 t; cvta.to.shared.u64 t, %1; cvt.u32.u64 %0, t; }" : "=r"(a) : "l"(p));
    return a;
}
__device__ __forceinline__ float frelu(float v) { return v > 0.0f ? v : 0.0f; }

__device__ __forceinline__ uint32_t split2(float a, float b, uint32_t& lop) {
    __nv_bfloat162 h = __floats2bfloat162_rn(a, b);
    float ra = a - __bfloat162float(h.x);
    float rb = b - __bfloat162float(h.y);
    __nv_bfloat162 l = __floats2bfloat162_rn(ra, rb);
    lop = *reinterpret_cast<uint32_t*>(&l);
    return *reinterpret_cast<uint32_t*>(&h);
}

#define LDSM4(r, addr)                                                      \
    asm volatile("ldmatrix.sync.aligned.m8n8.x4.shared.b16 "                \
                 "{%0,%1,%2,%3}, [%4];"                                     \
                 : "=r"((r)[0]), "=r"((r)[1]), "=r"((r)[2]), "=r"((r)[3])   \
                 : "r"(addr))

#define MMA16816(d, a, b)                                                   \
    asm volatile("mma.sync.aligned.m16n8k16.row.col.f32.bf16.bf16.f32 "     \
                 "{%0,%1,%2,%3}, {%4,%5,%6,%7}, {%8,%9}, {%0,%1,%2,%3};"    \
                 : "+f"((d)[0]), "+f"((d)[1]), "+f"((d)[2]), "+f"((d)[3])   \
                 : "r"((a)[0]), "r"((a)[1]), "r"((a)[2]), "r"((a)[3]),      \
                   "r"((b)[0]), "r"((b)[1]))

__global__ void __launch_bounds__(NTHREADS, 1)
vdc_mlp_pair(const float* __restrict__ features,
             const float* __restrict__ dirs,
             const float* __restrict__ embed_table,
             const float* __restrict__ W0, const float* __restrict__ b0,
             const float* __restrict__ W1, const float* __restrict__ b1,
             const float* __restrict__ W2, const float* __restrict__ b2,
             const int*   __restrict__ embed_ids,
             const int*   __restrict__ sh_degree_ptr,
             float* __restrict__ out,
             int N, int C)
{
    extern __shared__ char smem[];
    const uint32_t sb = smem_u32(smem);
    const int tid  = threadIdx.x;
    const int lane = tid & 31;
    const int w    = tid >> 5;
    const int pair = w >> 1;
    const int half = w & 1;          // column half: [64*half, 64*half+64)
    const int g    = lane >> 2;      // 0..7
    const int tig  = lane & 3;       // 0..3
    const int barid = pair + 1;      // named barriers 1..4

    float* sB1   = (float*)(smem + SM_B1);
    float* sW2   = (float*)(smem + SM_W2);
    float* sB2   = (float*)(smem + SM_B2);
    float* biasw = (float*)(smem + SM_BIASW) + pair * 128;
    float* part  = (float*)(smem + SM_PART) + pair * 96;   // [32][3]

    // ================= one-time weight staging =================
    if (tid < 128) sB1[tid] = b1[tid];
    if (tid < 96)  ((float4*)(smem + SM_W2))[tid] = ((const float4*)W2)[tid];
    if (tid == 0) { sB2[0] = b2[0]; sB2[1] = b2[1]; sB2[2] = b2[2]; }
    // W0t[n][k] = W0[16+k][n] (k = 0..47)
    for (int idx = tid; idx < 128 * 48; idx += NTHREADS) {
        int n = idx / 48, k = idx - n * 48;
        float v = W0[(16 + k) * 128 + n];
        __nv_bfloat16 h = __float2bfloat16(v);
        float r = v - __bfloat162float(h);
        uint32_t off = (uint32_t)(n * W0T_STRIDE + k * 2);
        *(__nv_bfloat16*)(smem + SM_W0T_HI + off) = h;
        *(__nv_bfloat16*)(smem + SM_W0T_LO + off) = __float2bfloat16(r);
    }
    // W1t[n][k] = W1[k][n]
    for (int idx = tid; idx < 128 * 128; idx += NTHREADS) {
        int n = idx >> 7, k = idx & 127;
        float v = W1[k * 128 + n];
        __nv_bfloat16 h = __float2bfloat16(v);
        float r = v - __bfloat162float(h);
        uint32_t off = (uint32_t)(n * W1T_STRIDE + k * 2);
        *(__nv_bfloat16*)(smem + SM_W1T_HI + off) = h;
        *(__nv_bfloat16*)(smem + SM_W1T_LO + off) = __float2bfloat16(r);
    }
    __syncthreads();

    // ---- per-thread addresses ----
    const uint32_t aSlab  = sb + SM_A_HI + pair * (32 * A_STRIDE);
    const uint32_t hSlab  = sb + SM_H_HI + pair * (32 * H_STRIDE);
    const uint32_t a1addr = aSlab + (lane & 15) * A_STRIDE + (lane >> 4) * 16;
    const uint32_t a2addr = hSlab + (lane & 15) * H_STRIDE + (lane >> 4) * 16;
    // B provider rows (own 64-col half): n = 64*half + brow (+np2*32, +16)
    const uint32_t brow = (uint32_t)(64 * half + (lane >> 4) * 8 + (lane & 7));
    const uint32_t bkof = ((lane >> 3) & 1) * 16;
    const uint32_t b0base = sb + SM_W0T_HI + brow * W0T_STRIDE + bkof;
    const uint32_t b1base = sb + SM_W1T_HI + brow * W1T_STRIDE + bkof;

    const int chunksPerCam = (N + 31) >> 5;
    const int totalChunks  = chunksPerCam * C;
    const int deg = sh_degree_ptr ? sh_degree_ptr[0] : 3;
    const int nb  = (deg + 1) * (deg + 1);
    const int gp  = blockIdx.x * NPAIRS + pair;
    const int gstride = gridDim.x * NPAIRS;
    int last_c = -1;

    const float bias2_0 = sB2[0], bias2_1 = sB2[1], bias2_2 = sB2[2];

    for (int ch = gp; ch < totalChunks; ch += gstride) {
        const int c  = ch / chunksPerCam;
        const int m0 = (ch - c * chunksPerCam) * 32;

        // ---- fused bias0 on camera change (each warp: its own 64 cols) ----
        if (c != last_c) {
            last_c = c;
            const float* e = embed_table + (size_t)embed_ids[c] * 16;
            #pragma unroll
            for (int i = 0; i < 2; i++) {
                int col = 64 * half + lane * 2 + i;
                float acc = b0[col];
                #pragma unroll
                for (int j = 0; j < 16; j++)
                    acc = fmaf(e[j], W0[j * 128 + col], acc);
                biasw[col] = acc;
            }
        }

        // ================= build A slab (this warp: 16 of 32 rows) =========
        {
            int r = half * 16 + (lane >> 1);
            int hh = lane & 1;
            int n = m0 + r;
            char* aHi = smem + SM_A_HI + pair * (32 * A_STRIDE);
            char* aLo = smem + SM_A_LO + pair * (32 * A_STRIDE);
            const float4* src = (const float4*)(features + (size_t)n * 32) + hh * 4;
            #pragma unroll
            for (int i = 0; i < 4; i++) {
                float4 v = (n < N) ? src[i] : make_float4(0.f, 0.f, 0.f, 0.f);
                uint32_t l0, l1;
                uint32_t h0 = split2(v.x, v.y, l0);
                uint32_t h1 = split2(v.z, v.w, l1);
                uint32_t off = (uint32_t)(r * A_STRIDE + hh * 32 + i * 8);
                *(uint2*)(aHi + off) = make_uint2(h0, h1);
                *(uint2*)(aLo + off) = make_uint2(l0, l1);
            }
            if (lane < 16) {
                int rr = half * 16 + lane;
                int nn = m0 + rr;
                float dx = 0.f, dy = 0.f, dz = 0.f;
                if (nn < N) {
                    const float* dp = dirs + ((size_t)c * N + nn) * 3;
                    dx = dp[0]; dy = dp[1]; dz = dp[2];
                }
                float norm = sqrtf(dx*dx + dy*dy + dz*dz);
                float inv  = 1.0f / fmaxf(norm, 1e-12f);
                float x = dx*inv, y = dy*inv, z = dz*inv;
                float z2     = z * z;
                float fTmp0B = -1.092548430592079f * z;
                float fC1    = x*x - y*y;
                float fS1    = 2.0f * x * y;
                float fTmp0C = -2.285228997322329f * z2 + 0.4570457994644658f;
                float fTmp1B = 1.445305721320277f * z;
                float fC2    = x*fC1 - y*fS1;
                float fS2    = x*fS1 + y*fC1;
                float sh[16];
                sh[0]  = 0.2820947917738781f;
                sh[1]  = -0.48860251190292f * y;
                sh[2]  =  0.48860251190292f * z;
                sh[3]  = -0.48860251190292f * x;
                sh[4]  =  0.5462742152960395f * fS1;
                sh[5]  =  fTmp0B * y;
                sh[6]  =  0.9461746957575601f * z2 - 0.3153915652525201f;
                sh[7]  =  fTmp0B * x;
                sh[8]  =  0.5462742152960395f * fC1;
                sh[9]  = -0.5900435899266435f * fS2;
                sh[10] =  fTmp1B * fS1;
                sh[11] =  fTmp0C * y;
                sh[12] =  z * (1.865881662950577f * z2 - 1.119528997770346f);
                sh[13] =  fTmp0C * x;
                sh[14] =  fTmp1B * fC1;
                sh[15] = -0.5900435899266435f * fC2;
                #pragma unroll
                for (int j = 0; j < 16; j++) if (j >= nb) sh[j] = 0.0f;
                #pragma unroll
                for (int j = 0; j < 4; j++) {
                    uint32_t l0, l1;
                    uint32_t h0 = split2(sh[4*j],     sh[4*j + 1], l0);
                    uint32_t h1 = split2(sh[4*j + 2], sh[4*j + 3], l1);
                    uint32_t off = (uint32_t)(rr * A_STRIDE + 64 + j * 8);
                    *(uint2*)(aHi + off) = make_uint2(h0, h1);
                    *(uint2*)(aLo + off) = make_uint2(l0, l1);
                }
            }
        }
        asm volatile("bar.sync %0, 64;" :: "r"(barid) : "memory");

        // ================= GEMM1: 32 x 64(own), K=48 =================
        float d[2][32];   // [mtile][ntile*4+q], ntile 0..7
        #pragma unroll
        for (int mt = 0; mt < 2; mt++)
            #pragma unroll
            for (int q = 0; q < 32; q++) d[mt][q] = 0.0f;

        #pragma unroll
        for (int kt = 0; kt < 3; kt++) {
            uint32_t ah[2][4], al[2][4];
            #pragma unroll
            for (int mt = 0; mt < 2; mt++) {
                uint32_t aa = a1addr + (uint32_t)(mt * 16 * A_STRIDE + kt * 32);
                LDSM4(ah[mt], aa);
                LDSM4(al[mt], aa + (SM_A_LO - SM_A_HI));
            }
            #pragma unroll
            for (int np2 = 0; np2 < 2; np2++) {
                uint32_t bh0[4], bl0[4], bh1[4], bl1[4];
                uint32_t ba = b0base + (uint32_t)(np2 * 32 * W0T_STRIDE + kt * 32);
                LDSM4(bh0, ba);
                LDSM4(bl0, ba + (SM_W0T_LO - SM_W0T_HI));
                LDSM4(bh1, ba + 16 * W0T_STRIDE);
                LDSM4(bl1, ba + 16 * W0T_STRIDE + (SM_W0T_LO - SM_W0T_HI));
                #pragma unroll
                for (int mt = 0; mt < 2; mt++) {
                    float* dd = d[mt] + np2 * 16;
                    MMA16816(dd + 0,  ah[mt], bh0);
                    MMA16816(dd + 4,  ah[mt], bh0 + 2);
                    MMA16816(dd + 8,  ah[mt], bh1);
                    MMA16816(dd + 12, ah[mt], bh1 + 2);
                    MMA16816(dd + 0,  ah[mt], bl0);
                    MMA16816(dd + 4,  ah[mt], bl0 + 2);
                    MMA16816(dd + 8,  ah[mt], bl1);
                    MMA16816(dd + 12, ah[mt], bl1 + 2);
                    MMA16816(dd + 0,  al[mt], bh0);
                    MMA16816(dd + 4,  al[mt], bh0 + 2);
                    MMA16816(dd + 8,  al[mt], bh1);
                    MMA16816(dd + 12, al[mt], bh1 + 2);
                }
            }
        }

        // ---- epilogue1: relu + fused bias -> H slab (own 64 cols, 32 rows) ----
        {
            char* hHi = smem + SM_H_HI + pair * (32 * H_STRIDE);
            char* hLo = smem + SM_H_LO + pair * (32 * H_STRIDE);
            #pragma unroll
            for (int mt = 0; mt < 2; mt++)
                #pragma unroll
                for (int nt = 0; nt < 8; nt++) {
                    int c0 = 64 * half + nt * 8 + tig * 2;
                    float bv0 = biasw[c0], bv1 = biasw[c0 + 1];
                    float* dd = &d[mt][nt * 4];
                    float f00 = frelu(dd[0] + bv0);
                    float f01 = frelu(dd[1] + bv1);
                    float f10 = frelu(dd[2] + bv0);
                    float f11 = frelu(dd[3] + bv1);
                    uint32_t l0, l1;
                    uint32_t h0 = split2(f00, f01, l0);
                    uint32_t h1 = split2(f10, f11, l1);
                    uint32_t o0 = (uint32_t)((mt * 16 + g) * H_STRIDE + c0 * 2);
                    uint32_t o1 = (uint32_t)((mt * 16 + g + 8) * H_STRIDE + c0 * 2);
                    *(uint32_t*)(hHi + o0) = h0;
                    *(uint32_t*)(hLo + o0) = l0;
                    *(uint32_t*)(hHi + o1) = h1;
                    *(uint32_t*)(hLo + o1) = l1;
                }
        }
        asm volatile("bar.sync %0, 64;" :: "r"(barid) : "memory");

        // ================= GEMM2: 32 x 64(own), K=128 =================
        #pragma unroll
        for (int mt = 0; mt < 2; mt++)
            #pragma unroll
            for (int q = 0; q < 32; q++) d[mt][q] = 0.0f;

        #pragma unroll
        for (int kt = 0; kt < 8; kt++) {
            uint32_t ah[2][4], al[2][4];
            #pragma unroll
            for (int mt = 0; mt < 2; mt++) {
                uint32_t aa = a2addr + (uint32_t)(mt * 16 * H_STRIDE + kt * 32);
                LDSM4(ah[mt], aa);
                LDSM4(al[mt], aa + (SM_H_LO - SM_H_HI));
            }
            #pragma unroll
            for (int np2 = 0; np2 < 2; np2++) {
                uint32_t bh0[4], bl0[4], bh1[4], bl1[4];
                uint32_t ba = b1base + (uint32_t)(np2 * 32 * W1T_STRIDE + kt * 32);
                LDSM4(bh0, ba);
                LDSM4(bl0, ba + (SM_W1T_LO - SM_W1T_HI));
                LDSM4(bh1, ba + 16 * W1T_STRIDE);
                LDSM4(bl1, ba + 16 * W1T_STRIDE + (SM_W1T_LO - SM_W1T_HI));
                #pragma unroll
                for (int mt = 0; mt < 2; mt++) {
                    float* dd = d[mt] + np2 * 16;
                    MMA16816(dd + 0,  ah[mt], bh0);
                    MMA16816(dd + 4,  ah[mt], bh0 + 2);
                    MMA16816(dd + 8,  ah[mt], bh1);
                    MMA16816(dd + 12, ah[mt], bh1 + 2);
                    MMA16816(dd + 0,  ah[mt], bl0);
                    MMA16816(dd + 4,  ah[mt], bl0 + 2);
                    MMA16816(dd + 8,  ah[mt], bl1);
                    MMA16816(dd + 12, ah[mt], bl1 + 2);
                    MMA16816(dd + 0,  al[mt], bh0);
                    MMA16816(dd + 4,  al[mt], bh0 + 2);
                    MMA16816(dd + 8,  al[mt], bh1);
                    MMA16816(dd + 12, al[mt], bh1 + 2);
                }
            }
        }

        // ---- epilogue2: relu + b1, project onto W2 (own 64 cols) ----
        {
            float o[2][2][3];   // [mtile][row 0/+8][rgb]
            #pragma unroll
            for (int mt = 0; mt < 2; mt++)
                #pragma unroll
                for (int r = 0; r < 2; r++)
                    o[mt][r][0] = o[mt][r][1] = o[mt][r][2] = 0.f;
            #pragma unroll
            for (int mt = 0; mt < 2; mt++)
                #pragma unroll
                for (int nt = 0; nt < 8; nt++) {
                    int c0 = 64 * half + nt * 8 + tig * 2;
                    float bv0 = sB1[c0], bv1 = sB1[c0 + 1];
                    float* dd = &d[mt][nt * 4];
                    float f00 = frelu(dd[0] + bv0);
                    float f01 = frelu(dd[1] + bv1);
                    float f10 = frelu(dd[2] + bv0);
                    float f11 = frelu(dd[3] + bv1);
                    float wa0 = sW2[c0*3+0], wa1 = sW2[c0*3+1], wa2 = sW2[c0*3+2];
                    float wb0 = sW2[(c0+1)*3+0], wb1 = sW2[(c0+1)*3+1], wb2 = sW2[(c0+1)*3+2];
                    o[mt][0][0] = fmaf(f00, wa0, fmaf(f01, wb0, o[mt][0][0]));
                    o[mt][0][1] = fmaf(f00, wa1, fmaf(f01, wb1, o[mt][0][1]));
                    o[mt][0][2] = fmaf(f00, wa2, fmaf(f01, wb2, o[mt][0][2]));
                    o[mt][1][0] = fmaf(f10, wa0, fmaf(f11, wb0, o[mt][1][0]));
                    o[mt][1][1] = fmaf(f10, wa1, fmaf(f11, wb1, o[mt][1][1]));
                    o[mt][1][2] = fmaf(f10, wa2, fmaf(f11, wb2, o[mt][1][2]));
                }
            // reduce over tig lanes (own 64 cols)
            #pragma unroll
            for (int mt = 0; mt < 2; mt++)
                #pragma unroll
                for (int r = 0; r < 2; r++)
                    #pragma unroll
                    for (int q = 0; q < 3; q++) {
                        float v = o[mt][r][q];
                        v += __shfl_xor_sync(0xffffffffu, v, 1);
                        v += __shfl_xor_sync(0xffffffffu, v, 2);
                        o[mt][r][q] = v;
                    }
            // half 1 publishes its partials
            if (half == 1 && tig == 0) {
                #pragma unroll
                for (int mt = 0; mt < 2; mt++)
                    #pragma unroll
                    for (int r = 0; r < 2; r++) {
                        int row = mt * 16 + g + r * 8;
                        part[row * 3 + 0] = o[mt][r][0];
                        part[row * 3 + 1] = o[mt][r][1];
                        part[row * 3 + 2] = o[mt][r][2];
                    }
            }
            asm volatile("bar.sync %0, 64;" :: "r"(barid) : "memory");
            // half 0 combines + stores
            if (half == 0 && tig == 0) {
                #pragma unroll
                for (int mt = 0; mt < 2; mt++)
                    #pragma unroll
                    for (int r = 0; r < 2; r++) {
                        int row = mt * 16 + g + r * 8;
                        int n = m0 + row;
                        if (n < N) {
                            size_t base = ((size_t)c * N + n) * 3;
                            out[base + 0] = o[mt][r][0] + part[row * 3 + 0] + bias2_0;
                            out[base + 1] = o[mt][r][1] + part[row * 3 + 1] + bias2_1;
                            out[base + 2] = o[mt][r][2] + part[row * 3 + 2] + bias2_2;
                        }
                    }
            }
        }
    }
}

extern "C" void kernel_launch(void* const* d_in, const int* in_sizes, int n_in,
                              void* d_out, int out_size)
{
    const float* features    = (const float*)d_in[0];
    const float* dirs        = (const float*)d_in[1];
    const float* embed_table = (const float*)d_in[2];
    const float* W0          = (const float*)d_in[3];
    const float* b0          = (const float*)d_in[4];
    const float* W1          = (const float*)d_in[5];
    const float* b1          = (const float*)d_in[6];
    const float* W2          = (const float*)d_in[7];
    const float* b2          = (const float*)d_in[8];
    const int*   embed_ids   = (const int*)d_in[9];
    const int*   shdeg       = (n_in > 10) ? (const int*)d_in[10] : nullptr;

    const int N = in_sizes[0] / 32;
    const int C = in_sizes[9];

    int sms = 148;
    cudaDeviceGetAttribute(&sms, cudaDevAttrMultiProcessorCount, 0);

    const int chunks = ((N + 31) / 32) * C;
    int grid = sms;
    int maxBlocks = (chunks + NPAIRS - 1) / NPAIRS;
    if (grid > maxBlocks) grid = maxBlocks;

    cudaFuncSetAttribute(vdc_mlp_pair,
                         cudaFuncAttributeMaxDynamicSharedMemorySize, SMEM_TOTAL);

    vdc_mlp_pair<<<grid, NTHREADS, SMEM_TOTAL>>>(
        features, dirs, embed_table, W0, b0, W1, b1, W2, b2,
        embed_ids, shdeg, (float*)d_out, N, C);
}

// round 14
// speedup vs baseline: 1.3519x; 1.3519x over previous
#include <cuda_runtime.h>
#include <cuda_fp16.h>
#include <stdint.h>

// Round 12: warp-independent FP16 2-term split HMMA kernel.
// A (activations) = single fp16; B (weights) = fp16 hi + fp16 lo.
// D = Ahi*(Bhi+Blo) => exact in B, error only from A's fp16 rounding (~2^-11).
// MMA count = 2/3 of the bf16 3-term version.

#define NTHREADS 256
#define NWARPS   8

// ---- smem byte offsets ----
#define SM_W0T_HI  0         // [128 n][48 k] f16, stride 112
#define SM_W0T_LO  14336
#define SM_W1T_HI  28672     // [128 n][128 k] f16, stride 272
#define SM_W1T_LO  63488
#define SM_A       98304     // 8 warps x [16][48+pad] f16, stride 112
#define SM_H       112640    // 8 warps x [16][128+pad] f16, stride 272
#define SM_B1      147456    // 128 f32
#define SM_W2      147968    // 384 f32
#define SM_B2      149504    // 3 f32 (+pad)
#define SM_BIASW   149520    // 8 warps x 128 f32 fused bias0
#define SMEM_TOTAL 153616

#define W0T_STRIDE 112
#define W1T_STRIDE 272
#define A_STRIDE   112
#define H_STRIDE   272

__device__ __forceinline__ uint32_t smem_u32(const void* p) {
    uint32_t a;
    asm("{ .reg .u64 t; cvta.to.shared.u64 t, %1; cvt.u32.u64 %0, t; }" : "=r"(a) : "l"(p));
    return a;
}
__device__ __forceinline__ float frelu(float v) { return v > 0.0f ? v : 0.0f; }

// pack two floats to f16x2 (no residual)
__device__ __forceinline__ uint32_t pack2h(float a, float b) {
    __half2 h = __floats2half2_rn(a, b);
    return *reinterpret_cast<uint32_t*>(&h);
}

#define LDSM4(r, addr)                                                      \
    asm volatile("ldmatrix.sync.aligned.m8n8.x4.shared.b16 "                \
                 "{%0,%1,%2,%3}, [%4];"                                     \
                 : "=r"((r)[0]), "=r"((r)[1]), "=r"((r)[2]), "=r"((r)[3])   \
                 : "r"(addr))

#define MMA16816(d, a, b)                                                   \
    asm volatile("mma.sync.aligned.m16n8k16.row.col.f32.f16.f16.f32 "       \
                 "{%0,%1,%2,%3}, {%4,%5,%6,%7}, {%8,%9}, {%0,%1,%2,%3};"    \
                 : "+f"((d)[0]), "+f"((d)[1]), "+f"((d)[2]), "+f"((d)[3])   \
                 : "r"((a)[0]), "r"((a)[1]), "r"((a)[2]), "r"((a)[3]),      \
                   "r"((b)[0]), "r"((b)[1]))

__global__ void __launch_bounds__(NTHREADS, 1)
vdc_mlp_fp16(const float* __restrict__ features,
             const float* __restrict__ dirs,
             const float* __restrict__ embed_table,
             const float* __restrict__ W0, const float* __restrict__ b0,
             const float* __restrict__ W1, const float* __restrict__ b1,
             const float* __restrict__ W2, const float* __restrict__ b2,
             const int*   __restrict__ embed_ids,
             const int*   __restrict__ sh_degree_ptr,
             float* __restrict__ out,
             int N, int C)
{
    extern __shared__ char smem[];
    const uint32_t sb = smem_u32(smem);
    const int tid  = threadIdx.x;
    const int lane = tid & 31;
    const int w    = tid >> 5;
    const int g    = lane >> 2;      // 0..7
    const int tig  = lane & 3;       // 0..3

    float* sB1   = (float*)(smem + SM_B1);
    float* sW2   = (float*)(smem + SM_W2);
    float* sB2   = (float*)(smem + SM_B2);
    float* biasw = (float*)(smem + SM_BIASW) + w * 128;

    // ================= one-time weight staging =================
    if (tid < 128) sB1[tid] = b1[tid];
    if (tid < 96)  ((float4*)(smem + SM_W2))[tid] = ((const float4*)W2)[tid];
    if (tid == 0) { sB2[0] = b2[0]; sB2[1] = b2[1]; sB2[2] = b2[2]; }
    // W0t[n][k] = W0[16+k][n], fp16 hi+lo  (k = 0..47)
    for (int idx = tid; idx < 128 * 48; idx += NTHREADS) {
        int n = idx / 48, k = idx - n * 48;
        float v = W0[(16 + k) * 128 + n];
        __half h = __float2half_rn(v);
        float r = v - __half2float(h);
        uint32_t off = (uint32_t)(n * W0T_STRIDE + k * 2);
        *(__half*)(smem + SM_W0T_HI + off) = h;
        *(__half*)(smem + SM_W0T_LO + off) = __float2half_rn(r);
    }
    // W1t[n][k] = W1[k][n]
    for (int idx = tid; idx < 128 * 128; idx += NTHREADS) {
        int n = idx >> 7, k = idx & 127;
        float v = W1[k * 128 + n];
        __half h = __float2half_rn(v);
        float r = v - __half2float(h);
        uint32_t off = (uint32_t)(n * W1T_STRIDE + k * 2);
        *(__half*)(smem + SM_W1T_HI + off) = h;
        *(__half*)(smem + SM_W1T_LO + off) = __float2half_rn(r);
    }
    __syncthreads();

    // ---- per-thread ldmatrix base addresses ----
    const uint32_t aSlab  = sb + SM_A + w * (16 * A_STRIDE);
    const uint32_t hSlab  = sb + SM_H + w * (16 * H_STRIDE);
    const uint32_t a1addr = aSlab + (lane & 15) * A_STRIDE + (lane >> 4) * 16;
    const uint32_t a2addr = hSlab + (lane & 15) * H_STRIDE + (lane >> 4) * 16;
    const uint32_t brow = ((lane >> 4) * 8 + (lane & 7));
    const uint32_t bkof = ((lane >> 3) & 1) * 16;
    const uint32_t b0base = sb + SM_W0T_HI + brow * W0T_STRIDE + bkof;
    const uint32_t b1base = sb + SM_W1T_HI + brow * W1T_STRIDE + bkof;

    const int chunksPerCam = (N + 15) >> 4;
    const int totalChunks  = chunksPerCam * C;
    const int deg = sh_degree_ptr ? sh_degree_ptr[0] : 3;
    const int nb  = (deg + 1) * (deg + 1);
    const int gw  = blockIdx.x * NWARPS + w;
    const int gstride = gridDim.x * NWARPS;
    int last_c = -1;

    const float bias2_0 = sB2[0], bias2_1 = sB2[1], bias2_2 = sB2[2];

    for (int ch = gw; ch < totalChunks; ch += gstride) {
        const int c  = ch / chunksPerCam;
        const int m0 = (ch - c * chunksPerCam) * 16;

        // ---- per-warp fused bias0 on camera change ----
        if (c != last_c) {
            last_c = c;
            const float* e = embed_table + (size_t)embed_ids[c] * 16;
            #pragma unroll
            for (int i = 0; i < 4; i++) {
                int col = lane * 4 + i;
                float acc = b0[col];
                #pragma unroll
                for (int j = 0; j < 16; j++)
                    acc = fmaf(e[j], W0[j * 128 + col], acc);
                biasw[col] = acc;
            }
        }

        // ================= build A slab (16 rows x 48 K, fp16) ============
        {
            int r = lane >> 1, hh = lane & 1;
            int n = m0 + r;
            const float4* src = (const float4*)(features + (size_t)n * 32) + hh * 4;
            char* aS = smem + SM_A + w * (16 * A_STRIDE);
            #pragma unroll
            for (int i = 0; i < 4; i++) {
                float4 v = (n < N) ? src[i] : make_float4(0.f, 0.f, 0.f, 0.f);
                uint32_t off = (uint32_t)(r * A_STRIDE + hh * 32 + i * 8);
                *(uint2*)(aS + off) = make_uint2(pack2h(v.x, v.y), pack2h(v.z, v.w));
            }
            // SH bases: lanes 0..15 each handle one row
            if (lane < 16) {
                int rr = lane;
                int nn = m0 + rr;
                float dx = 0.f, dy = 0.f, dz = 0.f;
                if (nn < N) {
                    const float* dp = dirs + ((size_t)c * N + nn) * 3;
                    dx = dp[0]; dy = dp[1]; dz = dp[2];
                }
                float norm = sqrtf(dx*dx + dy*dy + dz*dz);
                float inv  = 1.0f / fmaxf(norm, 1e-12f);
                float x = dx*inv, y = dy*inv, z = dz*inv;
                float z2     = z * z;
                float fTmp0B = -1.092548430592079f * z;
                float fC1    = x*x - y*y;
                float fS1    = 2.0f * x * y;
                float fTmp0C = -2.285228997322329f * z2 + 0.4570457994644658f;
                float fTmp1B = 1.445305721320277f * z;
                float fC2    = x*fC1 - y*fS1;
                float fS2    = x*fS1 + y*fC1;
                float sh[16];
                sh[0]  = 0.2820947917738781f;
                sh[1]  = -0.48860251190292f * y;
                sh[2]  =  0.48860251190292f * z;
                sh[3]  = -0.48860251190292f * x;
                sh[4]  =  0.5462742152960395f * fS1;
                sh[5]  =  fTmp0B * y;
                sh[6]  =  0.9461746957575601f * z2 - 0.3153915652525201f;
                sh[7]  =  fTmp0B * x;
                sh[8]  =  0.5462742152960395f * fC1;
                sh[9]  = -0.5900435899266435f * fS2;
                sh[10] =  fTmp1B * fS1;
                sh[11] =  fTmp0C * y;
                sh[12] =  z * (1.865881662950577f * z2 - 1.119528997770346f);
                sh[13] =  fTmp0C * x;
                sh[14] =  fTmp1B * fC1;
                sh[15] = -0.5900435899266435f * fC2;
                #pragma unroll
                for (int j = 0; j < 16; j++) if (j >= nb) sh[j] = 0.0f;
                #pragma unroll
                for (int j = 0; j < 4; j++) {
                    uint32_t off = (uint32_t)(rr * A_STRIDE + 64 + j * 8);
                    *(uint2*)(aS + off) = make_uint2(pack2h(sh[4*j], sh[4*j+1]),
                                                     pack2h(sh[4*j+2], sh[4*j+3]));
                }
            }
        }
        __syncwarp();

        // ================= GEMM1: 16 x 128, K=48, 2-term =================
        float d[16][4];
        #pragma unroll
        for (int i = 0; i < 16; i++)
            #pragma unroll
            for (int q = 0; q < 4; q++) d[i][q] = 0.0f;

        #pragma unroll
        for (int kt = 0; kt < 3; kt++) {
            uint32_t ah[4];
            LDSM4(ah, a1addr + kt * 32);
            #pragma unroll
            for (int np2 = 0; np2 < 4; np2++) {
                uint32_t bh0[4], bl0[4], bh1[4], bl1[4];
                uint32_t ba = b0base + (uint32_t)(np2 * 32 * W0T_STRIDE + kt * 32);
                LDSM4(bh0, ba);
                LDSM4(bl0, ba + (SM_W0T_LO - SM_W0T_HI));
                LDSM4(bh1, ba + 16 * W0T_STRIDE);
                LDSM4(bl1, ba + 16 * W0T_STRIDE + (SM_W0T_LO - SM_W0T_HI));
                float* d0 = d[np2*4 + 0]; float* d1 = d[np2*4 + 1];
                float* d2 = d[np2*4 + 2]; float* d3 = d[np2*4 + 3];
                MMA16816(d0, ah, bh0);     MMA16816(d1, ah, bh0 + 2);
                MMA16816(d2, ah, bh1);     MMA16816(d3, ah, bh1 + 2);
                MMA16816(d0, ah, bl0);     MMA16816(d1, ah, bl0 + 2);
                MMA16816(d2, ah, bl1);     MMA16816(d3, ah, bl1 + 2);
            }
        }

        // ---- epilogue1: relu + fused bias -> H slab (fp16) ----
        {
            char* hS = smem + SM_H + w * (16 * H_STRIDE);
            #pragma unroll
            for (int nt = 0; nt < 16; nt++) {
                int c0 = nt * 8 + tig * 2;
                float bv0 = biasw[c0], bv1 = biasw[c0 + 1];
                float f00 = frelu(d[nt][0] + bv0);
                float f01 = frelu(d[nt][1] + bv1);
                float f10 = frelu(d[nt][2] + bv0);
                float f11 = frelu(d[nt][3] + bv1);
                uint32_t o0 = (uint32_t)(g * H_STRIDE + c0 * 2);
                uint32_t o1 = (uint32_t)((g + 8) * H_STRIDE + c0 * 2);
                *(uint32_t*)(hS + o0) = pack2h(f00, f01);
                *(uint32_t*)(hS + o1) = pack2h(f10, f11);
            }
        }
        __syncwarp();

        // ================= GEMM2: 16 x 128, K=128, 2-term =================
        #pragma unroll
        for (int i = 0; i < 16; i++)
            #pragma unroll
            for (int q = 0; q < 4; q++) d[i][q] = 0.0f;

        #pragma unroll
        for (int kt = 0; kt < 8; kt++) {
            uint32_t ah[4];
            LDSM4(ah, a2addr + kt * 32);
            #pragma unroll
            for (int np2 = 0; np2 < 4; np2++) {
                uint32_t bh0[4], bl0[4], bh1[4], bl1[4];
                uint32_t ba = b1base + (uint32_t)(np2 * 32 * W1T_STRIDE + kt * 32);
                LDSM4(bh0, ba);
                LDSM4(bl0, ba + (SM_W1T_LO - SM_W1T_HI));
                LDSM4(bh1, ba + 16 * W1T_STRIDE);
                LDSM4(bl1, ba + 16 * W1T_STRIDE + (SM_W1T_LO - SM_W1T_HI));
                float* d0 = d[np2*4 + 0]; float* d1 = d[np2*4 + 1];
                float* d2 = d[np2*4 + 2]; float* d3 = d[np2*4 + 3];
                MMA16816(d0, ah, bh0);     MMA16816(d1, ah, bh0 + 2);
                MMA16816(d2, ah, bh1);     MMA16816(d3, ah, bh1 + 2);
                MMA16816(d0, ah, bl0);     MMA16816(d1, ah, bl0 + 2);
                MMA16816(d2, ah, bl1);     MMA16816(d3, ah, bl1 + 2);
            }
        }

        // ---- epilogue2: relu + b1, project onto W2, shfl-reduce, store ----
        {
            float o00 = 0.f, o01 = 0.f, o02 = 0.f;
            float o10 = 0.f, o11 = 0.f, o12 = 0.f;
            #pragma unroll
            for (int nt = 0; nt < 16; nt++) {
                int c0 = nt * 8 + tig * 2;
                float bv0 = sB1[c0], bv1 = sB1[c0 + 1];
                float f00 = frelu(d[nt][0] + bv0);
                float f01 = frelu(d[nt][1] + bv1);
                float f10 = frelu(d[nt][2] + bv0);
                float f11 = frelu(d[nt][3] + bv1);
                float wa0 = sW2[c0*3 + 0], wa1 = sW2[c0*3 + 1], wa2 = sW2[c0*3 + 2];
                float wb0 = sW2[(c0+1)*3 + 0], wb1 = sW2[(c0+1)*3 + 1], wb2 = sW2[(c0+1)*3 + 2];
                o00 = fmaf(f00, wa0, fmaf(f01, wb0, o00));
                o01 = fmaf(f00, wa1, fmaf(f01, wb1, o01));
                o02 = fmaf(f00, wa2, fmaf(f01, wb2, o02));
                o10 = fmaf(f10, wa0, fmaf(f11, wb0, o10));
                o11 = fmaf(f10, wa1, fmaf(f11, wb1, o11));
                o12 = fmaf(f10, wa2, fmaf(f11, wb2, o12));
            }
            o00 += __shfl_xor_sync(0xffffffffu, o00, 1);
            o00 += __shfl_xor_sync(0xffffffffu, o00, 2);
            o01 += __shfl_xor_sync(0xffffffffu, o01, 1);
            o01 += __shfl_xor_sync(0xffffffffu, o01, 2);
            o02 += __shfl_xor_sync(0xffffffffu, o02, 1);
            o02 += __shfl_xor_sync(0xffffffffu, o02, 2);
            o10 += __shfl_xor_sync(0xffffffffu, o10, 1);
            o10 += __shfl_xor_sync(0xffffffffu, o10, 2);
            o11 += __shfl_xor_sync(0xffffffffu, o11, 1);
            o11 += __shfl_xor_sync(0xffffffffu, o11, 2);
            o12 += __shfl_xor_sync(0xffffffffu, o12, 1);
            o12 += __shfl_xor_sync(0xffffffffu, o12, 2);
            if (tig == 0) {
                int n0 = m0 + g;
                if (n0 < N) {
                    size_t base = ((size_t)c * N + n0) * 3;
                    out[base + 0] = o00 + bias2_0;
                    out[base + 1] = o01 + bias2_1;
                    out[base + 2] = o02 + bias2_2;
                }
                int n1 = m0 + g + 8;
                if (n1 < N) {
                    size_t base = ((size_t)c * N + n1) * 3;
                    out[base + 0] = o10 + bias2_0;
                    out[base + 1] = o11 + bias2_1;
                    out[base + 2] = o12 + bias2_2;
                }
            }
        }
        __syncwarp();
    }
}

extern "C" void kernel_launch(void* const* d_in, const int* in_sizes, int n_in,
                              void* d_out, int out_size)
{
    const float* features    = (const float*)d_in[0];
    const float* dirs        = (const float*)d_in[1];
    const float* embed_table = (const float*)d_in[2];
    const float* W0          = (const float*)d_in[3];
    const float* b0          = (const float*)d_in[4];
    const float* W1          = (const float*)d_in[5];
    const float* b1          = (const float*)d_in[6];
    const float* W2          = (const float*)d_in[7];
    const float* b2          = (const float*)d_in[8];
    const int*   embed_ids   = (const int*)d_in[9];
    const int*   shdeg       = (n_in > 10) ? (const int*)d_in[10] : nullptr;

    const int N = in_sizes[0] / 32;
    const int C = in_sizes[9];

    int sms = 148;
    cudaDeviceGetAttribute(&sms, cudaDevAttrMultiProcessorCount, 0);

    const int chunks = ((N + 15) / 16) * C;
    int grid = sms;
    int maxBlocks = (chunks + NWARPS - 1) / NWARPS;
    if (grid > maxBlocks) grid = maxBlocks;

    cudaFuncSetAttribute(vdc_mlp_fp16,
                         cudaFuncAttributeMaxDynamicSharedMemorySize, SMEM_TOTAL);

    vdc_mlp_fp16<<<grid, NTHREADS, SMEM_TOTAL>>>(
        features, dirs, embed_table, W0, b0, W1, b1, W2, b2,
        embed_ids, shdeg, (float*)d_out, N, C);
}